// round 15
// baseline (speedup 1.0000x reference)
#include <cuda_runtime.h>
#include <cuda_fp16.h>
#include <cstdint>
#include <cstddef>

#define T_TOK 16384
#define D_DIM 1024
#define F_DIM 4096
#define E_EXP 8
#define ALPHA_F 2.0f

// ---- device scratch (allocation-free; all fp16 hi-only) ----
__device__ __half g_hid[(size_t)T_TOK * F_DIM];
__device__ __half g_x[(size_t)T_TOK * D_DIM];
__device__ __half g_wi[(size_t)F_DIM * D_DIM];
__device__ __half g_wo[(size_t)D_DIM * F_DIM];
__device__ __half g_U1[T_TOK * 32];
__device__ __half g_U2[T_TOK * 32];
__device__ __half g_wbc1[F_DIM * 16];
__device__ __half g_wbe1[E_EXP * F_DIM * 16];
__device__ __half g_wbc2[D_DIM * 16];
__device__ __half g_wbe2[E_EXP * D_DIM * 16];
__device__ __half g_wac1[16 * D_DIM];
__device__ __half g_wae1[E_EXP * 16 * D_DIM];
__device__ __half g_wac2[16 * F_DIM];
__device__ __half g_wae2[E_EXP * 16 * F_DIM];

// ---------------- helpers ----------------
__device__ __forceinline__ uint32_t smem_u32(const void* p) {
    uint32_t a;
    asm("{ .reg .u64 t; cvta.to.shared.u64 t, %1; cvt.u32.u64 %0, t; }" : "=r"(a) : "l"(p));
    return a;
}
__device__ __forceinline__ void ldsm_x4(uint32_t* r, uint32_t addr) {
    asm volatile("ldmatrix.sync.aligned.m8n8.x4.shared.b16 {%0,%1,%2,%3}, [%4];"
                 : "=r"(r[0]), "=r"(r[1]), "=r"(r[2]), "=r"(r[3]) : "r"(addr));
}
__device__ __forceinline__ void mma_f16(float* d, const uint32_t* a, const uint32_t* b) {
    asm volatile(
        "mma.sync.aligned.m16n8k16.row.col.f32.f16.f16.f32 "
        "{%0,%1,%2,%3},{%4,%5,%6,%7},{%8,%9},{%0,%1,%2,%3};"
        : "+f"(d[0]), "+f"(d[1]), "+f"(d[2]), "+f"(d[3])
        : "r"(a[0]), "r"(a[1]), "r"(a[2]), "r"(a[3]), "r"(b[0]), "r"(b[1]));
}
__device__ __forceinline__ void cpa16(uint32_t dst, const void* src) {
    asm volatile("cp.async.cg.shared.global [%0], [%1], 16;" :: "r"(dst), "l"(src));
}
__device__ __forceinline__ void cpa_commit() {
    asm volatile("cp.async.commit_group;" ::: "memory");
}
template <int NW>
__device__ __forceinline__ void cpa_wait() {
    asm volatile("cp.async.wait_group %0;" :: "n"(NW) : "memory");
}

// ================ pre-pass: fp32 -> fp16, multi-segment ================
struct SplitSeg { const float* src; __half* dst; int n; };
struct SplitArgs { SplitSeg seg[8]; };

__global__ __launch_bounds__(256) void split_multi(SplitArgs a) {
    const SplitSeg g = a.seg[blockIdx.y];
    int i = (blockIdx.x * 256 + threadIdx.x) * 8;
    if (i >= g.n) return;
    float v[8];
    *(float4*)&v[0] = *(const float4*)(g.src + i);
    *(float4*)&v[4] = *(const float4*)(g.src + i + 4);
    uint32_t hw[4];
#pragma unroll
    for (int j = 0; j < 4; j++) {
        __half2 ph{__float2half_rn(v[2 * j]), __float2half_rn(v[2 * j + 1])};
        hw[j] = *reinterpret_cast<uint32_t*>(&ph);
    }
    *(uint4*)(g.dst + i) = make_uint4(hw[0], hw[1], hw[2], hw[3]);
}

// ============ skinny HMMA lora GEMM: U = ALPHA * X @ [Wac;Wae[e]]^T ============
#define LSTG 12288
#define LB_OFF 8192

__global__ __launch_bounds__(128) void lora_gemm(
    const __half* __restrict__ X, const __half* __restrict__ Wac,
    const __half* __restrict__ Wae, const int* __restrict__ eids,
    __half* __restrict__ U, int K)
{
    extern __shared__ char smraw[];
    uint32_t sd0 = smem_u32(smraw);
    char* smem = smraw + (((sd0 + 1023u) & ~1023u) - sd0);
    const uint32_t Sb = smem_u32(smem);

    const int tid = threadIdx.x, wid = tid >> 5, lane = tid & 31;
    const int m0 = blockIdx.x * 64;
    const int e = eids[m0 >> 9];
    const int m_w = wid * 16;

    const int arow = lane & 15, ac8 = (lane >> 4) * 16;
    const int brow_base = ((lane >> 4) & 1) * 8 + (lane & 7);
    const int bk8 = ((lane >> 3) & 1) * 16;

    float acc[4][4];
#pragma unroll
    for (int i = 0; i < 4; i++)
#pragma unroll
        for (int q = 0; q < 4; q++) acc[i][q] = 0.f;

    const int KCH = K >> 6;
    const int srow = tid >> 1, shf = tid & 1;

    auto load_stage = [&](int ch, int s) {
        const uint32_t Ab = Sb + s * LSTG;
        const int kc = ch << 6;
        {
            const __half* sh = X + (size_t)(m0 + srow) * K + kc + shf * 32;
            const uint32_t ro = (uint32_t)srow * 128, xm = (uint32_t)(srow & 7) << 4;
#pragma unroll
            for (int j = 0; j < 4; j++)
                cpa16(Ab + ro + (((uint32_t)(shf * 64 + j * 16)) ^ xm), sh + j * 8);
        }
        if (tid < 64) {
            const int row = tid >> 1, bhf = tid & 1;
            const __half* sb = (row < 16)
                ? (Wac + (size_t)row * K + kc + bhf * 32)
                : (Wae + ((size_t)e * 16 + (row - 16)) * (size_t)K + kc + bhf * 32);
            const uint32_t ro = (uint32_t)row * 128, xm = (uint32_t)(row & 7) << 4;
#pragma unroll
            for (int j = 0; j < 4; j++)
                cpa16(Ab + LB_OFF + ro + (((uint32_t)(bhf * 64 + j * 16)) ^ xm), sb + j * 8);
        }
    };

    auto compute_stage = [&](int s) {
        const uint32_t Ab = Sb + s * LSTG;
#pragma unroll
        for (int ks = 0; ks < 4; ks++) {
            const int kb = ks * 32;
            uint32_t ah[4], bh[2][4];
            {
                int row = m_w + arow;
                ldsm_x4(ah, Ab + (uint32_t)row * 128 +
                            ((uint32_t)(kb + ac8) ^ ((uint32_t)(row & 7) << 4)));
            }
#pragma unroll
            for (int p = 0; p < 2; p++) {
                int row = p * 16 + brow_base;
                ldsm_x4(bh[p], Ab + LB_OFF + (uint32_t)row * 128 +
                               ((uint32_t)(kb + bk8) ^ ((uint32_t)(row & 7) << 4)));
            }
#pragma unroll
            for (int ni = 0; ni < 4; ni++)
                mma_f16(acc[ni], ah, &bh[ni >> 1][(ni & 1) * 2]);
        }
    };

    load_stage(0, 0);
    cpa_commit();
    for (int ch = 0; ch < KCH; ch++) {
        if (ch + 1 < KCH) {
            load_stage(ch + 1, (ch + 1) & 1);
            cpa_commit();
            cpa_wait<1>();
        } else {
            cpa_wait<0>();
        }
        __syncthreads();
        compute_stage(ch & 1);
        __syncthreads();
    }

    const int er = lane >> 2, ec = (lane & 3) * 2;
#pragma unroll
    for (int ni = 0; ni < 4; ni++) {
#pragma unroll
        for (int hrow = 0; hrow < 2; hrow++) {
            int gr = m0 + m_w + er + hrow * 8;
            int gc = ni * 8 + ec;
            __half2 v{__float2half_rn(ALPHA_F * acc[ni][hrow * 2]),
                      __float2half_rn(ALPHA_F * acc[ni][hrow * 2 + 1])};
            *reinterpret_cast<__half2*>(U + (size_t)gr * 32 + gc) = v;
        }
    }
}

// ===== fp16 GEMM + fused LoRA: CTA 256x128, 8 warps @ 64x64, 1 CTA/SM =====
// Fragment double-buffered across k-steps; 3-stage cp.async; R11 loop schedule.
// Stage: A 32K | B 16K = 48KB x3 = 144KB.
#define GSTG 49152
#define GB_OFF 32768
#define GSMEM (3 * GSTG + 1024)

template <int MODE>  // 1: relu -> fp16 out; 0: fp32 out
__global__ __launch_bounds__(256, 1) void gemm_cp(
    const __half* __restrict__ A, const __half* __restrict__ B,
    const __half* __restrict__ U,
    const __half* __restrict__ Wbc, const __half* __restrict__ Wbe,
    const int* __restrict__ eids,
    float* __restrict__ outF, __half* __restrict__ outH, int N, int K)
{
    extern __shared__ char smraw[];
    uint32_t sd0 = smem_u32(smraw);
    char* smem = smraw + (((sd0 + 1023u) & ~1023u) - sd0);
    const uint32_t Sb = smem_u32(smem);

    const int tid = threadIdx.x, wid = tid >> 5, lane = tid & 31;
    const int m0 = blockIdx.y * 256, n0 = blockIdx.x * 128;
    const int e = eids[m0 >> 9];

    // 8 warps: 4M x 2N, each 64x64
    const int m_w = (wid >> 1) * 64, n_w = (wid & 1) * 64;
    const int arow = lane & 15, ac8 = (lane >> 4) * 16;
    const int brow_base = ((lane >> 4) & 1) * 8 + (lane & 7);
    const int bk8 = ((lane >> 3) & 1) * 16;

    float acc[4][8][4];
#pragma unroll
    for (int i = 0; i < 4; i++)
#pragma unroll
        for (int j = 0; j < 8; j++)
#pragma unroll
            for (int q = 0; q < 4; q++) acc[i][j][q] = 0.f;

    const int KCH = K >> 6, NCH = KCH + 1;

    // staging: A 256 rows (thread = row, 128B); B 128 rows (2 thr/row)
    auto load_stage = [&](int ch, int s) {
        const uint32_t Ab = Sb + (uint32_t)s * GSTG;
        if (ch < KCH) {
            const int kc = ch << 6;
            {
                const int row = tid;
                const uint32_t ro = (uint32_t)row * 128, xm = (uint32_t)(row & 7) << 4;
                const __half* sa = A + (size_t)(m0 + row) * K + kc;
#pragma unroll
                for (int j = 0; j < 8; j++)
                    cpa16(Ab + ro + (((uint32_t)(j * 16)) ^ xm), sa + j * 8);
            }
            {
                const int row = tid >> 1, hf = tid & 1;
                const uint32_t ro = (uint32_t)row * 128, xm = (uint32_t)(row & 7) << 4;
                const __half* sb = B + (size_t)(n0 + row) * K + kc + hf * 32;
#pragma unroll
                for (int j = 0; j < 4; j++)
                    cpa16(Ab + GB_OFF + ro + (((uint32_t)(hf * 64 + j * 16)) ^ xm), sb + j * 8);
            }
        } else {
            {   // A-lora: U rows (32 fp16 = 64B)
                const int row = tid;
                const uint32_t ro = (uint32_t)row * 128, xm = (uint32_t)(row & 7) << 4;
                const __half* su = U + (size_t)(m0 + row) * 32;
#pragma unroll
                for (int j = 0; j < 4; j++)
                    cpa16(Ab + ro + (((uint32_t)(j * 16)) ^ xm), su + j * 8);
            }
            {   // B-lora: k 0:16 = Wbc (hf=0), 16:32 = Wbe[e] (hf=1)
                const int row = tid >> 1, hf = tid & 1;
                const uint32_t ro = (uint32_t)row * 128, xm = (uint32_t)(row & 7) << 4;
                const __half* sb = hf
                    ? (Wbe + (size_t)e * N * 16 + (size_t)(n0 + row) * 16)
                    : (Wbc + (size_t)(n0 + row) * 16);
#pragma unroll
                for (int j = 0; j < 2; j++)
                    cpa16(Ab + GB_OFF + ro + (((uint32_t)(hf * 32 + j * 16)) ^ xm), sb + j * 8);
            }
        }
    };

    // fragment loader for one k-step
    auto load_frags = [&](uint32_t Ab, int ks, uint32_t (*ah)[4], uint32_t (*bh)[4]) {
        const int kb = ks * 32;
#pragma unroll
        for (int mi = 0; mi < 4; mi++) {
            int row = m_w + mi * 16 + arow;
            ldsm_x4(ah[mi], Ab + (uint32_t)row * 128 +
                            ((uint32_t)(kb + ac8) ^ ((uint32_t)(row & 7) << 4)));
        }
#pragma unroll
        for (int p = 0; p < 4; p++) {
            int row = n_w + p * 16 + brow_base;
            ldsm_x4(bh[p], Ab + GB_OFF + (uint32_t)row * 128 +
                           ((uint32_t)(kb + bk8) ^ ((uint32_t)(row & 7) << 4)));
        }
    };

    auto compute_stage = [&](int s, int nks) {
        const uint32_t Ab = Sb + (uint32_t)s * GSTG;
        uint32_t ah[2][4][4], bh[2][4][4];
        load_frags(Ab, 0, ah[0], bh[0]);
#pragma unroll
        for (int ks = 0; ks < 4; ks++) {
            if (ks >= nks) break;
            const int cur = ks & 1;
            if (ks + 1 < nks) load_frags(Ab, ks + 1, ah[cur ^ 1], bh[cur ^ 1]);
#pragma unroll
            for (int mi = 0; mi < 4; mi++)
#pragma unroll
                for (int ni = 0; ni < 8; ni++)
                    mma_f16(acc[mi][ni], ah[cur][mi], &bh[cur][ni >> 1][(ni & 1) * 2]);
        }
    };

    // ---- 3-stage pipeline, R11 schedule: compute first, then load ch+2 ----
    load_stage(0, 0);
    cpa_commit();
    load_stage(1, 1);
    cpa_commit();
    int s3 = 0;
    for (int ch = 0; ch < NCH; ch++) {
        if (ch + 1 < NCH) cpa_wait<1>();
        else cpa_wait<0>();
        __syncthreads();
        compute_stage(s3, (ch < KCH) ? 4 : 2);
        if (ch + 2 < NCH) {
            int sn = s3 + 2;
            if (sn >= 3) sn -= 3;
            load_stage(ch + 2, sn);
            cpa_commit();
        }
        if (++s3 == 3) s3 = 0;
    }

    // ---- epilogue ----
    const int er = lane >> 2, ec = (lane & 3) * 2;
#pragma unroll
    for (int mi = 0; mi < 4; mi++) {
#pragma unroll
        for (int ni = 0; ni < 8; ni++) {
            float* d = acc[mi][ni];
            int gr0 = m0 + m_w + mi * 16 + er;
            int gc = n0 + n_w + ni * 8 + ec;
#pragma unroll
            for (int hrow = 0; hrow < 2; hrow++) {
                int gr = gr0 + hrow * 8;
                if (MODE == 1) {
                    float v0 = fmaxf(d[hrow * 2], 0.f), v1 = fmaxf(d[hrow * 2 + 1], 0.f);
                    __half2 ph{__float2half_rn(v0), __float2half_rn(v1)};
                    *reinterpret_cast<__half2*>(outH + (size_t)gr * N + gc) = ph;
                } else {
                    float2 v{d[hrow * 2], d[hrow * 2 + 1]};
                    *reinterpret_cast<float2*>(outF + (size_t)gr * N + gc) = v;
                }
            }
        }
    }
}

// =============================== launch ===============================
extern "C" void kernel_launch(void* const* d_in, const int* in_sizes, int n_in,
                              void* d_out, int out_size)
{
    (void)in_sizes; (void)n_in; (void)out_size;
    const float* x     = (const float*)d_in[0];
    const int*   eids  = (const int*)d_in[1];
    const float* wi    = (const float*)d_in[2];
    const float* wo    = (const float*)d_in[3];
    const float* cwi_a = (const float*)d_in[4];
    const float* cwi_b = (const float*)d_in[5];
    const float* cwo_a = (const float*)d_in[6];
    const float* cwo_b = (const float*)d_in[7];
    const float* ewi_a = (const float*)d_in[8];
    const float* ewi_b = (const float*)d_in[9];
    const float* ewo_a = (const float*)d_in[10];
    const float* ewo_b = (const float*)d_in[11];
    float* out = (float*)d_out;

    __half *hid, *xh, *wih, *woh, *U1, *U2;
    __half *wbc1, *wbe1, *wbc2, *wbe2, *wac1, *wae1, *wac2, *wae2;
    cudaGetSymbolAddress((void**)&hid, g_hid);
    cudaGetSymbolAddress((void**)&xh, g_x);
    cudaGetSymbolAddress((void**)&wih, g_wi);
    cudaGetSymbolAddress((void**)&woh, g_wo);
    cudaGetSymbolAddress((void**)&U1, g_U1);
    cudaGetSymbolAddress((void**)&U2, g_U2);
    cudaGetSymbolAddress((void**)&wbc1, g_wbc1);
    cudaGetSymbolAddress((void**)&wbe1, g_wbe1);
    cudaGetSymbolAddress((void**)&wbc2, g_wbc2);
    cudaGetSymbolAddress((void**)&wbe2, g_wbe2);
    cudaGetSymbolAddress((void**)&wac1, g_wac1);
    cudaGetSymbolAddress((void**)&wae1, g_wae1);
    cudaGetSymbolAddress((void**)&wac2, g_wac2);
    cudaGetSymbolAddress((void**)&wae2, g_wae2);

    cudaFuncSetAttribute(gemm_cp<1>, cudaFuncAttributeMaxDynamicSharedMemorySize, GSMEM);
    cudaFuncSetAttribute(gemm_cp<0>, cudaFuncAttributeMaxDynamicSharedMemorySize, GSMEM);
    const int LSMEM = 2 * LSTG + 1024;
    cudaFuncSetAttribute(lora_gemm, cudaFuncAttributeMaxDynamicSharedMemorySize, LSMEM);

    // ---- merged pre-splits: 2 launches ----
    {
        SplitArgs a{};
        a.seg[0] = { x,  xh,  T_TOK * D_DIM };
        a.seg[1] = { wi, wih, F_DIM * D_DIM };
        a.seg[2] = { wo, woh, D_DIM * F_DIM };
        dim3 g((T_TOK * D_DIM) / 2048, 3);
        split_multi<<<g, 256>>>(a);
    }
    {
        SplitArgs a{};
        a.seg[0] = { cwi_b, wbc1, F_DIM * 16 };
        a.seg[1] = { ewi_b, wbe1, E_EXP * F_DIM * 16 };
        a.seg[2] = { cwo_b, wbc2, D_DIM * 16 };
        a.seg[3] = { ewo_b, wbe2, E_EXP * D_DIM * 16 };
        a.seg[4] = { cwi_a, wac1, 16 * D_DIM };
        a.seg[5] = { ewi_a, wae1, E_EXP * 16 * D_DIM };
        a.seg[6] = { cwo_a, wac2, 16 * F_DIM };
        a.seg[7] = { ewo_a, wae2, E_EXP * 16 * F_DIM };
        dim3 g((E_EXP * F_DIM * 16) / 2048, 8);
        split_multi<<<g, 256>>>(a);
    }

    // stage 1
    lora_gemm<<<T_TOK / 64, 128, LSMEM>>>(xh, wac1, wae1, eids, U1, D_DIM);
    dim3 g1(F_DIM / 128, T_TOK / 256);
    gemm_cp<1><<<g1, 256, GSMEM>>>(xh, wih, U1, wbc1, wbe1, eids,
                                   nullptr, hid, F_DIM, D_DIM);

    // stage 2
    lora_gemm<<<T_TOK / 64, 128, LSMEM>>>(hid, wac2, wae2, eids, U2, F_DIM);
    dim3 g2(D_DIM / 128, T_TOK / 256);
    gemm_cp<0><<<g2, 256, GSMEM>>>(hid, woh, U2, wbc2, wbe2, eids,
                                   out, nullptr, D_DIM, F_DIM);
}

// round 16
// speedup vs baseline: 1.4151x; 1.4151x over previous
#include <cuda_runtime.h>
#include <cuda_fp16.h>
#include <cstdint>
#include <cstddef>

#define T_TOK 16384
#define D_DIM 1024
#define F_DIM 4096
#define E_EXP 8
#define ALPHA_F 2.0f

// ---- device scratch (allocation-free; all fp16 hi-only) ----
__device__ __half g_hid[(size_t)T_TOK * F_DIM];
__device__ __half g_x[(size_t)T_TOK * D_DIM];
__device__ __half g_wi[(size_t)F_DIM * D_DIM];
__device__ __half g_wo[(size_t)D_DIM * F_DIM];
__device__ __half g_U1[T_TOK * 32];
__device__ __half g_U2[T_TOK * 32];
__device__ __half g_wbc1[F_DIM * 16];
__device__ __half g_wbe1[E_EXP * F_DIM * 16];
__device__ __half g_wbc2[D_DIM * 16];
__device__ __half g_wbe2[E_EXP * D_DIM * 16];
__device__ __half g_wac1[16 * D_DIM];
__device__ __half g_wae1[E_EXP * 16 * D_DIM];
__device__ __half g_wac2[16 * F_DIM];
__device__ __half g_wae2[E_EXP * 16 * F_DIM];

// ---------------- helpers ----------------
__device__ __forceinline__ uint32_t smem_u32(const void* p) {
    uint32_t a;
    asm("{ .reg .u64 t; cvta.to.shared.u64 t, %1; cvt.u32.u64 %0, t; }" : "=r"(a) : "l"(p));
    return a;
}
__device__ __forceinline__ void ldsm_x4(uint32_t* r, uint32_t addr) {
    asm volatile("ldmatrix.sync.aligned.m8n8.x4.shared.b16 {%0,%1,%2,%3}, [%4];"
                 : "=r"(r[0]), "=r"(r[1]), "=r"(r[2]), "=r"(r[3]) : "r"(addr));
}
__device__ __forceinline__ void mma_f16(float* d, const uint32_t* a, const uint32_t* b) {
    asm volatile(
        "mma.sync.aligned.m16n8k16.row.col.f32.f16.f16.f32 "
        "{%0,%1,%2,%3},{%4,%5,%6,%7},{%8,%9},{%0,%1,%2,%3};"
        : "+f"(d[0]), "+f"(d[1]), "+f"(d[2]), "+f"(d[3])
        : "r"(a[0]), "r"(a[1]), "r"(a[2]), "r"(a[3]), "r"(b[0]), "r"(b[1]));
}
__device__ __forceinline__ void cpa16(uint32_t dst, const void* src) {
    asm volatile("cp.async.cg.shared.global [%0], [%1], 16;" :: "r"(dst), "l"(src));
}
__device__ __forceinline__ void cpa_commit() {
    asm volatile("cp.async.commit_group;" ::: "memory");
}
template <int NW>
__device__ __forceinline__ void cpa_wait() {
    asm volatile("cp.async.wait_group %0;" :: "n"(NW) : "memory");
}

// ================ pre-pass: fp32 -> fp16, multi-segment ================
struct SplitSeg { const float* src; __half* dst; int n; };
struct SplitArgs { SplitSeg seg[8]; };

__global__ __launch_bounds__(256) void split_multi(SplitArgs a) {
    const SplitSeg g = a.seg[blockIdx.y];
    int i = (blockIdx.x * 256 + threadIdx.x) * 8;
    if (i >= g.n) return;
    float v[8];
    *(float4*)&v[0] = *(const float4*)(g.src + i);
    *(float4*)&v[4] = *(const float4*)(g.src + i + 4);
    uint32_t hw[4];
#pragma unroll
    for (int j = 0; j < 4; j++) {
        __half2 ph{__float2half_rn(v[2 * j]), __float2half_rn(v[2 * j + 1])};
        hw[j] = *reinterpret_cast<uint32_t*>(&ph);
    }
    *(uint4*)(g.dst + i) = make_uint4(hw[0], hw[1], hw[2], hw[3]);
}

// ============ skinny HMMA lora GEMM: U = ALPHA * X @ [Wac;Wae[e]]^T ============
#define LSTG 12288
#define LB_OFF 8192

__global__ __launch_bounds__(128) void lora_gemm(
    const __half* __restrict__ X, const __half* __restrict__ Wac,
    const __half* __restrict__ Wae, const int* __restrict__ eids,
    __half* __restrict__ U, int K)
{
    extern __shared__ char smraw[];
    uint32_t sd0 = smem_u32(smraw);
    char* smem = smraw + (((sd0 + 1023u) & ~1023u) - sd0);
    const uint32_t Sb = smem_u32(smem);

    const int tid = threadIdx.x, wid = tid >> 5, lane = tid & 31;
    const int m0 = blockIdx.x * 64;
    const int e = eids[m0 >> 9];
    const int m_w = wid * 16;

    const int arow = lane & 15, ac8 = (lane >> 4) * 16;
    const int brow_base = ((lane >> 4) & 1) * 8 + (lane & 7);
    const int bk8 = ((lane >> 3) & 1) * 16;

    float acc[4][4];
#pragma unroll
    for (int i = 0; i < 4; i++)
#pragma unroll
        for (int q = 0; q < 4; q++) acc[i][q] = 0.f;

    const int KCH = K >> 6;
    const int srow = tid >> 1, shf = tid & 1;

    auto load_stage = [&](int ch, int s) {
        const uint32_t Ab = Sb + s * LSTG;
        const int kc = ch << 6;
        {
            const __half* sh = X + (size_t)(m0 + srow) * K + kc + shf * 32;
            const uint32_t ro = (uint32_t)srow * 128, xm = (uint32_t)(srow & 7) << 4;
#pragma unroll
            for (int j = 0; j < 4; j++)
                cpa16(Ab + ro + (((uint32_t)(shf * 64 + j * 16)) ^ xm), sh + j * 8);
        }
        if (tid < 64) {
            const int row = tid >> 1, bhf = tid & 1;
            const __half* sb = (row < 16)
                ? (Wac + (size_t)row * K + kc + bhf * 32)
                : (Wae + ((size_t)e * 16 + (row - 16)) * (size_t)K + kc + bhf * 32);
            const uint32_t ro = (uint32_t)row * 128, xm = (uint32_t)(row & 7) << 4;
#pragma unroll
            for (int j = 0; j < 4; j++)
                cpa16(Ab + LB_OFF + ro + (((uint32_t)(bhf * 64 + j * 16)) ^ xm), sb + j * 8);
        }
    };

    auto compute_stage = [&](int s) {
        const uint32_t Ab = Sb + s * LSTG;
#pragma unroll
        for (int ks = 0; ks < 4; ks++) {
            const int kb = ks * 32;
            uint32_t ah[4], bh[2][4];
            {
                int row = m_w + arow;
                ldsm_x4(ah, Ab + (uint32_t)row * 128 +
                            ((uint32_t)(kb + ac8) ^ ((uint32_t)(row & 7) << 4)));
            }
#pragma unroll
            for (int p = 0; p < 2; p++) {
                int row = p * 16 + brow_base;
                ldsm_x4(bh[p], Ab + LB_OFF + (uint32_t)row * 128 +
                               ((uint32_t)(kb + bk8) ^ ((uint32_t)(row & 7) << 4)));
            }
#pragma unroll
            for (int ni = 0; ni < 4; ni++)
                mma_f16(acc[ni], ah, &bh[ni >> 1][(ni & 1) * 2]);
        }
    };

    load_stage(0, 0);
    cpa_commit();
    for (int ch = 0; ch < KCH; ch++) {
        if (ch + 1 < KCH) {
            load_stage(ch + 1, (ch + 1) & 1);
            cpa_commit();
            cpa_wait<1>();
        } else {
            cpa_wait<0>();
        }
        __syncthreads();
        compute_stage(ch & 1);
        __syncthreads();
    }

    const int er = lane >> 2, ec = (lane & 3) * 2;
#pragma unroll
    for (int ni = 0; ni < 4; ni++) {
#pragma unroll
        for (int hrow = 0; hrow < 2; hrow++) {
            int gr = m0 + m_w + er + hrow * 8;
            int gc = ni * 8 + ec;
            __half2 v{__float2half_rn(ALPHA_F * acc[ni][hrow * 2]),
                      __float2half_rn(ALPHA_F * acc[ni][hrow * 2 + 1])};
            *reinterpret_cast<__half2*>(U + (size_t)gr * 32 + gc) = v;
        }
    }
}

// ===== fp16 GEMM + fused LoRA: R14 geometry (8 warps @ 32x64, 2 CTAs/SM) =====
// NEW: fragment rotation — ah double-buffered across ks, bh rolling 2-slot.
// Stage: A 16K | B 16K = 32KB x3.
#define GSTG 32768
#define GB_OFF 16384
#define GSMEM (3 * GSTG + 1024)

template <int MODE>  // 1: relu -> fp16 out; 0: fp32 out
__global__ __launch_bounds__(256, 2) void gemm_cp(
    const __half* __restrict__ A, const __half* __restrict__ B,
    const __half* __restrict__ U,
    const __half* __restrict__ Wbc, const __half* __restrict__ Wbe,
    const int* __restrict__ eids,
    float* __restrict__ outF, __half* __restrict__ outH, int N, int K)
{
    extern __shared__ char smraw[];
    uint32_t sd0 = smem_u32(smraw);
    char* smem = smraw + (((sd0 + 1023u) & ~1023u) - sd0);
    const uint32_t Sb = smem_u32(smem);

    const int tid = threadIdx.x, wid = tid >> 5, lane = tid & 31;
    const int m0 = blockIdx.y * 128, n0 = blockIdx.x * 128;
    const int e = eids[m0 >> 9];

    const int m_w = (wid >> 1) * 32, n_w = (wid & 1) * 64;
    const int arow = lane & 15, ac8 = (lane >> 4) * 16;
    const int brow_base = ((lane >> 4) & 1) * 8 + (lane & 7);
    const int bk8 = ((lane >> 3) & 1) * 16;

    float acc[2][8][4];
#pragma unroll
    for (int i = 0; i < 2; i++)
#pragma unroll
        for (int j = 0; j < 8; j++)
#pragma unroll
            for (int q = 0; q < 4; q++) acc[i][j][q] = 0.f;

    const int KCH = K >> 6, NCH = KCH + 1;
    const int srow = tid >> 1, shf = tid & 1;

    auto load_stage = [&](int ch, int s) {
        const uint32_t Ab = Sb + (uint32_t)s * GSTG;
        const uint32_t ro = (uint32_t)srow * 128, xm = (uint32_t)(srow & 7) << 4;
        if (ch < KCH) {
            const int kc = ch << 6;
            const __half* sa = A + (size_t)(m0 + srow) * K + kc + shf * 32;
            const __half* sb = B + (size_t)(n0 + srow) * K + kc + shf * 32;
#pragma unroll
            for (int j = 0; j < 4; j++) {
                uint32_t d = ((uint32_t)(shf * 64 + j * 16)) ^ xm;
                cpa16(Ab + ro + d, sa + j * 8);
                cpa16(Ab + GB_OFF + ro + d, sb + j * 8);
            }
        } else {
            const __half* su = U + (size_t)(m0 + srow) * 32 + shf * 16;
            const __half* sb = shf
                ? (Wbe + (size_t)e * N * 16 + (size_t)(n0 + srow) * 16)
                : (Wbc + (size_t)(n0 + srow) * 16);
#pragma unroll
            for (int j = 0; j < 2; j++) {
                uint32_t d = ((uint32_t)(shf * 32 + j * 16)) ^ xm;
                cpa16(Ab + ro + d, su + j * 8);
                cpa16(Ab + GB_OFF + ro + d, sb + j * 8);
            }
        }
    };

    // A-fragment loader (both mi) for a k-step
    auto load_ah = [&](uint32_t Ab, int ks, uint32_t (*a)[4]) {
        const int kb = ks * 32;
#pragma unroll
        for (int mi = 0; mi < 2; mi++) {
            int row = m_w + mi * 16 + arow;
            ldsm_x4(a[mi], Ab + (uint32_t)row * 128 +
                           ((uint32_t)(kb + ac8) ^ ((uint32_t)(row & 7) << 4)));
        }
    };
    // B-fragment loader for n8-pair p
    auto load_bh = [&](uint32_t Ab, int kb, int p, uint32_t* b) {
        int row = n_w + p * 16 + brow_base;
        ldsm_x4(b, Ab + GB_OFF + (uint32_t)row * 128 +
                   ((uint32_t)(kb + bk8) ^ ((uint32_t)(row & 7) << 4)));
    };

    auto compute_stage = [&](int s, int nks) {
        const uint32_t Ab = Sb + (uint32_t)s * GSTG;
        uint32_t ah[2][2][4];   // double-buffered across ks
        uint32_t bh[2][4];      // rolling 2-slot pair buffer
        load_ah(Ab, 0, ah[0]);
#pragma unroll
        for (int ks = 0; ks < 4; ks++) {
            if (ks >= nks) break;
            const int cur = ks & 1;
            const int kb = ks * 32;
            if (ks + 1 < nks) load_ah(Ab, ks + 1, ah[cur ^ 1]);  // overlaps this ks's MMAs
            load_bh(Ab, kb, 0, bh[0]);
            load_bh(Ab, kb, 1, bh[1]);
#pragma unroll
            for (int p = 0; p < 4; p++) {
                const int slot = p & 1;
#pragma unroll
                for (int mi = 0; mi < 2; mi++) {
                    mma_f16(acc[mi][2 * p],     ah[cur][mi], &bh[slot][0]);
                    mma_f16(acc[mi][2 * p + 1], ah[cur][mi], &bh[slot][2]);
                }
                if (p + 2 < 4) load_bh(Ab, kb, p + 2, bh[slot]);  // overlaps pair p+1's MMAs
            }
        }
    };

    // ---- 3-stage pipeline, R11/R14 schedule ----
    load_stage(0, 0);
    cpa_commit();
    load_stage(1, 1);
    cpa_commit();
    int s3 = 0;
    for (int ch = 0; ch < NCH; ch++) {
        if (ch + 1 < NCH) cpa_wait<1>();
        else cpa_wait<0>();
        __syncthreads();
        compute_stage(s3, (ch < KCH) ? 4 : 2);
        if (ch + 2 < NCH) {
            int sn = s3 + 2;
            if (sn >= 3) sn -= 3;
            load_stage(ch + 2, sn);
            cpa_commit();
        }
        if (++s3 == 3) s3 = 0;
    }

    // ---- epilogue ----
    const int er = lane >> 2, ec = (lane & 3) * 2;
#pragma unroll
    for (int mi = 0; mi < 2; mi++) {
#pragma unroll
        for (int ni = 0; ni < 8; ni++) {
            float* d = acc[mi][ni];
            int gr0 = m0 + m_w + mi * 16 + er;
            int gc = n0 + n_w + ni * 8 + ec;
#pragma unroll
            for (int hrow = 0; hrow < 2; hrow++) {
                int gr = gr0 + hrow * 8;
                if (MODE == 1) {
                    float v0 = fmaxf(d[hrow * 2], 0.f), v1 = fmaxf(d[hrow * 2 + 1], 0.f);
                    __half2 ph{__float2half_rn(v0), __float2half_rn(v1)};
                    *reinterpret_cast<__half2*>(outH + (size_t)gr * N + gc) = ph;
                } else {
                    float2 v{d[hrow * 2], d[hrow * 2 + 1]};
                    *reinterpret_cast<float2*>(outF + (size_t)gr * N + gc) = v;
                }
            }
        }
    }
}

// =============================== launch ===============================
extern "C" void kernel_launch(void* const* d_in, const int* in_sizes, int n_in,
                              void* d_out, int out_size)
{
    (void)in_sizes; (void)n_in; (void)out_size;
    const float* x     = (const float*)d_in[0];
    const int*   eids  = (const int*)d_in[1];
    const float* wi    = (const float*)d_in[2];
    const float* wo    = (const float*)d_in[3];
    const float* cwi_a = (const float*)d_in[4];
    const float* cwi_b = (const float*)d_in[5];
    const float* cwo_a = (const float*)d_in[6];
    const float* cwo_b = (const float*)d_in[7];
    const float* ewi_a = (const float*)d_in[8];
    const float* ewi_b = (const float*)d_in[9];
    const float* ewo_a = (const float*)d_in[10];
    const float* ewo_b = (const float*)d_in[11];
    float* out = (float*)d_out;

    __half *hid, *xh, *wih, *woh, *U1, *U2;
    __half *wbc1, *wbe1, *wbc2, *wbe2, *wac1, *wae1, *wac2, *wae2;
    cudaGetSymbolAddress((void**)&hid, g_hid);
    cudaGetSymbolAddress((void**)&xh, g_x);
    cudaGetSymbolAddress((void**)&wih, g_wi);
    cudaGetSymbolAddress((void**)&woh, g_wo);
    cudaGetSymbolAddress((void**)&U1, g_U1);
    cudaGetSymbolAddress((void**)&U2, g_U2);
    cudaGetSymbolAddress((void**)&wbc1, g_wbc1);
    cudaGetSymbolAddress((void**)&wbe1, g_wbe1);
    cudaGetSymbolAddress((void**)&wbc2, g_wbc2);
    cudaGetSymbolAddress((void**)&wbe2, g_wbe2);
    cudaGetSymbolAddress((void**)&wac1, g_wac1);
    cudaGetSymbolAddress((void**)&wae1, g_wae1);
    cudaGetSymbolAddress((void**)&wac2, g_wac2);
    cudaGetSymbolAddress((void**)&wae2, g_wae2);

    cudaFuncSetAttribute(gemm_cp<1>, cudaFuncAttributeMaxDynamicSharedMemorySize, GSMEM);
    cudaFuncSetAttribute(gemm_cp<0>, cudaFuncAttributeMaxDynamicSharedMemorySize, GSMEM);
    const int LSMEM = 2 * LSTG + 1024;
    cudaFuncSetAttribute(lora_gemm, cudaFuncAttributeMaxDynamicSharedMemorySize, LSMEM);

    // ---- merged pre-splits: 2 launches ----
    {
        SplitArgs a{};
        a.seg[0] = { x,  xh,  T_TOK * D_DIM };
        a.seg[1] = { wi, wih, F_DIM * D_DIM };
        a.seg[2] = { wo, woh, D_DIM * F_DIM };
        dim3 g((T_TOK * D_DIM) / 2048, 3);
        split_multi<<<g, 256>>>(a);
    }
    {
        SplitArgs a{};
        a.seg[0] = { cwi_b, wbc1, F_DIM * 16 };
        a.seg[1] = { ewi_b, wbe1, E_EXP * F_DIM * 16 };
        a.seg[2] = { cwo_b, wbc2, D_DIM * 16 };
        a.seg[3] = { ewo_b, wbe2, E_EXP * D_DIM * 16 };
        a.seg[4] = { cwi_a, wac1, 16 * D_DIM };
        a.seg[5] = { ewi_a, wae1, E_EXP * 16 * D_DIM };
        a.seg[6] = { cwo_a, wac2, 16 * F_DIM };
        a.seg[7] = { ewo_a, wae2, E_EXP * 16 * F_DIM };
        dim3 g((E_EXP * F_DIM * 16) / 2048, 8);
        split_multi<<<g, 256>>>(a);
    }

    // stage 1
    lora_gemm<<<T_TOK / 64, 128, LSMEM>>>(xh, wac1, wae1, eids, U1, D_DIM);
    dim3 g1(F_DIM / 128, T_TOK / 128);
    gemm_cp<1><<<g1, 256, GSMEM>>>(xh, wih, U1, wbc1, wbe1, eids,
                                   nullptr, hid, F_DIM, D_DIM);

    // stage 2
    lora_gemm<<<T_TOK / 64, 128, LSMEM>>>(hid, wac2, wae2, eids, U2, F_DIM);
    dim3 g2(D_DIM / 128, T_TOK / 128);
    gemm_cp<0><<<g2, 256, GSMEM>>>(hid, woh, U2, wbc2, wbe2, eids,
                                   out, nullptr, D_DIM, F_DIM);
}

// round 17
// speedup vs baseline: 1.4553x; 1.0284x over previous
#include <cuda_runtime.h>
#include <cuda_fp16.h>
#include <cstdint>
#include <cstddef>

#define T_TOK 16384
#define D_DIM 1024
#define F_DIM 4096
#define E_EXP 8
#define ALPHA_F 2.0f

// ---- device scratch (allocation-free; all fp16 hi-only) ----
__device__ __half g_hid[(size_t)T_TOK * F_DIM];
__device__ __half g_x[(size_t)T_TOK * D_DIM];
__device__ __half g_wi[(size_t)F_DIM * D_DIM];
__device__ __half g_wo[(size_t)D_DIM * F_DIM];
__device__ __half g_U1[T_TOK * 32];
__device__ __half g_U2[T_TOK * 32];
__device__ float g_Up[4 * T_TOK * 32];   // split-K partials (fp32)
__device__ __half g_wbc1[F_DIM * 16];
__device__ __half g_wbe1[E_EXP * F_DIM * 16];
__device__ __half g_wbc2[D_DIM * 16];
__device__ __half g_wbe2[E_EXP * D_DIM * 16];
__device__ __half g_wac1[16 * D_DIM];
__device__ __half g_wae1[E_EXP * 16 * D_DIM];
__device__ __half g_wac2[16 * F_DIM];
__device__ __half g_wae2[E_EXP * 16 * F_DIM];

// ---------------- helpers ----------------
__device__ __forceinline__ uint32_t smem_u32(const void* p) {
    uint32_t a;
    asm("{ .reg .u64 t; cvta.to.shared.u64 t, %1; cvt.u32.u64 %0, t; }" : "=r"(a) : "l"(p));
    return a;
}
__device__ __forceinline__ void ldsm_x4(uint32_t* r, uint32_t addr) {
    asm volatile("ldmatrix.sync.aligned.m8n8.x4.shared.b16 {%0,%1,%2,%3}, [%4];"
                 : "=r"(r[0]), "=r"(r[1]), "=r"(r[2]), "=r"(r[3]) : "r"(addr));
}
__device__ __forceinline__ void mma_f16(float* d, const uint32_t* a, const uint32_t* b) {
    asm volatile(
        "mma.sync.aligned.m16n8k16.row.col.f32.f16.f16.f32 "
        "{%0,%1,%2,%3},{%4,%5,%6,%7},{%8,%9},{%0,%1,%2,%3};"
        : "+f"(d[0]), "+f"(d[1]), "+f"(d[2]), "+f"(d[3])
        : "r"(a[0]), "r"(a[1]), "r"(a[2]), "r"(a[3]), "r"(b[0]), "r"(b[1]));
}
__device__ __forceinline__ void cpa16(uint32_t dst, const void* src) {
    asm volatile("cp.async.cg.shared.global [%0], [%1], 16;" :: "r"(dst), "l"(src));
}
__device__ __forceinline__ void cpa_commit() {
    asm volatile("cp.async.commit_group;" ::: "memory");
}
template <int NW>
__device__ __forceinline__ void cpa_wait() {
    asm volatile("cp.async.wait_group %0;" :: "n"(NW) : "memory");
}

// ================ pre-pass: fp32 -> fp16, multi-segment ================
struct SplitSeg { const float* src; __half* dst; int n; };
struct SplitArgs { SplitSeg seg[8]; };

__global__ __launch_bounds__(256) void split_multi(SplitArgs a) {
    const SplitSeg g = a.seg[blockIdx.y];
    int i = (blockIdx.x * 256 + threadIdx.x) * 8;
    if (i >= g.n) return;
    float v[8];
    *(float4*)&v[0] = *(const float4*)(g.src + i);
    *(float4*)&v[4] = *(const float4*)(g.src + i + 4);
    uint32_t hw[4];
#pragma unroll
    for (int j = 0; j < 4; j++) {
        __half2 ph{__float2half_rn(v[2 * j]), __float2half_rn(v[2 * j + 1])};
        hw[j] = *reinterpret_cast<uint32_t*>(&ph);
    }
    *(uint4*)(g.dst + i) = make_uint4(hw[0], hw[1], hw[2], hw[3]);
}

// ===== split-K skinny HMMA lora GEMM: Up[z] = X[:, z-slice] @ Wa^T (fp32) =====
// grid.x = M/64, grid.y = KS (K-slices). Combine kernel sums + scales + fp16.
#define LSTG 12288
#define LB_OFF 8192

__global__ __launch_bounds__(128) void lora_gemm_part(
    const __half* __restrict__ X, const __half* __restrict__ Wac,
    const __half* __restrict__ Wae, const int* __restrict__ eids,
    float* __restrict__ Up, int K, int Kpart)
{
    extern __shared__ char smraw[];
    uint32_t sd0 = smem_u32(smraw);
    char* smem = smraw + (((sd0 + 1023u) & ~1023u) - sd0);
    const uint32_t Sb = smem_u32(smem);

    const int tid = threadIdx.x, wid = tid >> 5, lane = tid & 31;
    const int m0 = blockIdx.x * 64;
    const int k0 = blockIdx.y * Kpart;
    float* Uout = Up + (size_t)blockIdx.y * T_TOK * 32;
    const int e = eids[m0 >> 9];
    const int m_w = wid * 16;

    const int arow = lane & 15, ac8 = (lane >> 4) * 16;
    const int brow_base = ((lane >> 4) & 1) * 8 + (lane & 7);
    const int bk8 = ((lane >> 3) & 1) * 16;

    float acc[4][4];
#pragma unroll
    for (int i = 0; i < 4; i++)
#pragma unroll
        for (int q = 0; q < 4; q++) acc[i][q] = 0.f;

    const int KCH = Kpart >> 6;
    const int srow = tid >> 1, shf = tid & 1;

    auto load_stage = [&](int ch, int s) {
        const uint32_t Ab = Sb + s * LSTG;
        const int kc = k0 + (ch << 6);
        {
            const __half* sh = X + (size_t)(m0 + srow) * K + kc + shf * 32;
            const uint32_t ro = (uint32_t)srow * 128, xm = (uint32_t)(srow & 7) << 4;
#pragma unroll
            for (int j = 0; j < 4; j++)
                cpa16(Ab + ro + (((uint32_t)(shf * 64 + j * 16)) ^ xm), sh + j * 8);
        }
        if (tid < 64) {
            const int row = tid >> 1, bhf = tid & 1;
            const __half* sb = (row < 16)
                ? (Wac + (size_t)row * K + kc + bhf * 32)
                : (Wae + ((size_t)e * 16 + (row - 16)) * (size_t)K + kc + bhf * 32);
            const uint32_t ro = (uint32_t)row * 128, xm = (uint32_t)(row & 7) << 4;
#pragma unroll
            for (int j = 0; j < 4; j++)
                cpa16(Ab + LB_OFF + ro + (((uint32_t)(bhf * 64 + j * 16)) ^ xm), sb + j * 8);
        }
    };

    auto compute_stage = [&](int s) {
        const uint32_t Ab = Sb + s * LSTG;
#pragma unroll
        for (int ks = 0; ks < 4; ks++) {
            const int kb = ks * 32;
            uint32_t ah[4], bh[2][4];
            {
                int row = m_w + arow;
                ldsm_x4(ah, Ab + (uint32_t)row * 128 +
                            ((uint32_t)(kb + ac8) ^ ((uint32_t)(row & 7) << 4)));
            }
#pragma unroll
            for (int p = 0; p < 2; p++) {
                int row = p * 16 + brow_base;
                ldsm_x4(bh[p], Ab + LB_OFF + (uint32_t)row * 128 +
                               ((uint32_t)(kb + bk8) ^ ((uint32_t)(row & 7) << 4)));
            }
#pragma unroll
            for (int ni = 0; ni < 4; ni++)
                mma_f16(acc[ni], ah, &bh[ni >> 1][(ni & 1) * 2]);
        }
    };

    load_stage(0, 0);
    cpa_commit();
    for (int ch = 0; ch < KCH; ch++) {
        if (ch + 1 < KCH) {
            load_stage(ch + 1, (ch + 1) & 1);
            cpa_commit();
            cpa_wait<1>();
        } else {
            cpa_wait<0>();
        }
        __syncthreads();
        compute_stage(ch & 1);
        __syncthreads();
    }

    const int er = lane >> 2, ec = (lane & 3) * 2;
#pragma unroll
    for (int ni = 0; ni < 4; ni++) {
#pragma unroll
        for (int hrow = 0; hrow < 2; hrow++) {
            int gr = m0 + m_w + er + hrow * 8;
            int gc = ni * 8 + ec;
            float2 v{acc[ni][hrow * 2], acc[ni][hrow * 2 + 1]};
            *reinterpret_cast<float2*>(Uout + (size_t)gr * 32 + gc) = v;
        }
    }
}

// combine: U = fp16(ALPHA * sum_z Up[z]),  512K elements
__global__ __launch_bounds__(256) void u_combine(
    const float* __restrict__ Up, __half* __restrict__ U, int KS)
{
    int i = (blockIdx.x * 256 + threadIdx.x) * 4;
    if (i >= T_TOK * 32) return;
    float4 s = *(const float4*)(Up + i);
    for (int z = 1; z < KS; z++) {
        float4 p = *(const float4*)(Up + (size_t)z * T_TOK * 32 + i);
        s.x += p.x; s.y += p.y; s.z += p.z; s.w += p.w;
    }
    __half2 h0{__float2half_rn(ALPHA_F * s.x), __float2half_rn(ALPHA_F * s.y)};
    __half2 h1{__float2half_rn(ALPHA_F * s.z), __float2half_rn(ALPHA_F * s.w)};
    uint32_t w0 = *reinterpret_cast<uint32_t*>(&h0);
    uint32_t w1 = *reinterpret_cast<uint32_t*>(&h1);
    *reinterpret_cast<uint2*>(U + i) = make_uint2(w0, w1);
}

// ===== fp16 GEMM + fused LoRA: R14 PROVEN (8 warps @ 32x64, 2 CTAs/SM) =====
#define GSTG 32768
#define GB_OFF 16384
#define GSMEM (3 * GSTG + 1024)

template <int MODE>  // 1: relu -> fp16 out; 0: fp32 out
__global__ __launch_bounds__(256, 2) void gemm_cp(
    const __half* __restrict__ A, const __half* __restrict__ B,
    const __half* __restrict__ U,
    const __half* __restrict__ Wbc, const __half* __restrict__ Wbe,
    const int* __restrict__ eids,
    float* __restrict__ outF, __half* __restrict__ outH, int N, int K)
{
    extern __shared__ char smraw[];
    uint32_t sd0 = smem_u32(smraw);
    char* smem = smraw + (((sd0 + 1023u) & ~1023u) - sd0);
    const uint32_t Sb = smem_u32(smem);

    const int tid = threadIdx.x, wid = tid >> 5, lane = tid & 31;
    const int m0 = blockIdx.y * 128, n0 = blockIdx.x * 128;
    const int e = eids[m0 >> 9];

    const int m_w = (wid >> 1) * 32, n_w = (wid & 1) * 64;
    const int arow = lane & 15, ac8 = (lane >> 4) * 16;
    const int brow_base = ((lane >> 4) & 1) * 8 + (lane & 7);
    const int bk8 = ((lane >> 3) & 1) * 16;

    float acc[2][8][4];
#pragma unroll
    for (int i = 0; i < 2; i++)
#pragma unroll
        for (int j = 0; j < 8; j++)
#pragma unroll
            for (int q = 0; q < 4; q++) acc[i][j][q] = 0.f;

    const int KCH = K >> 6, NCH = KCH + 1;
    const int srow = tid >> 1, shf = tid & 1;

    auto load_stage = [&](int ch, int s) {
        const uint32_t Ab = Sb + (uint32_t)s * GSTG;
        const uint32_t ro = (uint32_t)srow * 128, xm = (uint32_t)(srow & 7) << 4;
        if (ch < KCH) {
            const int kc = ch << 6;
            const __half* sa = A + (size_t)(m0 + srow) * K + kc + shf * 32;
            const __half* sb = B + (size_t)(n0 + srow) * K + kc + shf * 32;
#pragma unroll
            for (int j = 0; j < 4; j++) {
                uint32_t d = ((uint32_t)(shf * 64 + j * 16)) ^ xm;
                cpa16(Ab + ro + d, sa + j * 8);
                cpa16(Ab + GB_OFF + ro + d, sb + j * 8);
            }
        } else {
            const __half* su = U + (size_t)(m0 + srow) * 32 + shf * 16;
            const __half* sb = shf
                ? (Wbe + (size_t)e * N * 16 + (size_t)(n0 + srow) * 16)
                : (Wbc + (size_t)(n0 + srow) * 16);
#pragma unroll
            for (int j = 0; j < 2; j++) {
                uint32_t d = ((uint32_t)(shf * 32 + j * 16)) ^ xm;
                cpa16(Ab + ro + d, su + j * 8);
                cpa16(Ab + GB_OFF + ro + d, sb + j * 8);
            }
        }
    };

    auto compute_stage = [&](int s, int nks) {
        const uint32_t Ab = Sb + (uint32_t)s * GSTG;
#pragma unroll
        for (int ks = 0; ks < 4; ks++) {
            if (ks >= nks) break;
            const int kb = ks * 32;
            uint32_t ah[2][4], bh[4][4];
#pragma unroll
            for (int mi = 0; mi < 2; mi++) {
                int row = m_w + mi * 16 + arow;
                ldsm_x4(ah[mi], Ab + (uint32_t)row * 128 +
                                ((uint32_t)(kb + ac8) ^ ((uint32_t)(row & 7) << 4)));
            }
#pragma unroll
            for (int p = 0; p < 4; p++) {
                int row = n_w + p * 16 + brow_base;
                ldsm_x4(bh[p], Ab + GB_OFF + (uint32_t)row * 128 +
                               ((uint32_t)(kb + bk8) ^ ((uint32_t)(row & 7) << 4)));
            }
#pragma unroll
            for (int mi = 0; mi < 2; mi++)
#pragma unroll
                for (int ni = 0; ni < 8; ni++)
                    mma_f16(acc[mi][ni], ah[mi], &bh[ni >> 1][(ni & 1) * 2]);
        }
    };

    // ---- 3-stage pipeline, R11/R14 schedule ----
    load_stage(0, 0);
    cpa_commit();
    load_stage(1, 1);
    cpa_commit();
    int s3 = 0;
    for (int ch = 0; ch < NCH; ch++) {
        if (ch + 1 < NCH) cpa_wait<1>();
        else cpa_wait<0>();
        __syncthreads();
        compute_stage(s3, (ch < KCH) ? 4 : 2);
        if (ch + 2 < NCH) {
            int sn = s3 + 2;
            if (sn >= 3) sn -= 3;
            load_stage(ch + 2, sn);
            cpa_commit();
        }
        if (++s3 == 3) s3 = 0;
    }

    // ---- epilogue ----
    const int er = lane >> 2, ec = (lane & 3) * 2;
#pragma unroll
    for (int mi = 0; mi < 2; mi++) {
#pragma unroll
        for (int ni = 0; ni < 8; ni++) {
            float* d = acc[mi][ni];
            int gr0 = m0 + m_w + mi * 16 + er;
            int gc = n0 + n_w + ni * 8 + ec;
#pragma unroll
            for (int hrow = 0; hrow < 2; hrow++) {
                int gr = gr0 + hrow * 8;
                if (MODE == 1) {
                    float v0 = fmaxf(d[hrow * 2], 0.f), v1 = fmaxf(d[hrow * 2 + 1], 0.f);
                    __half2 ph{__float2half_rn(v0), __float2half_rn(v1)};
                    *reinterpret_cast<__half2*>(outH + (size_t)gr * N + gc) = ph;
                } else {
                    float2 v{d[hrow * 2], d[hrow * 2 + 1]};
                    *reinterpret_cast<float2*>(outF + (size_t)gr * N + gc) = v;
                }
            }
        }
    }
}

// =============================== launch ===============================
extern "C" void kernel_launch(void* const* d_in, const int* in_sizes, int n_in,
                              void* d_out, int out_size)
{
    (void)in_sizes; (void)n_in; (void)out_size;
    const float* x     = (const float*)d_in[0];
    const int*   eids  = (const int*)d_in[1];
    const float* wi    = (const float*)d_in[2];
    const float* wo    = (const float*)d_in[3];
    const float* cwi_a = (const float*)d_in[4];
    const float* cwi_b = (const float*)d_in[5];
    const float* cwo_a = (const float*)d_in[6];
    const float* cwo_b = (const float*)d_in[7];
    const float* ewi_a = (const float*)d_in[8];
    const float* ewi_b = (const float*)d_in[9];
    const float* ewo_a = (const float*)d_in[10];
    const float* ewo_b = (const float*)d_in[11];
    float* out = (float*)d_out;

    __half *hid, *xh, *wih, *woh, *U1, *U2;
    __half *wbc1, *wbe1, *wbc2, *wbe2, *wac1, *wae1, *wac2, *wae2;
    float* Up;
    cudaGetSymbolAddress((void**)&hid, g_hid);
    cudaGetSymbolAddress((void**)&xh, g_x);
    cudaGetSymbolAddress((void**)&wih, g_wi);
    cudaGetSymbolAddress((void**)&woh, g_wo);
    cudaGetSymbolAddress((void**)&U1, g_U1);
    cudaGetSymbolAddress((void**)&U2, g_U2);
    cudaGetSymbolAddress((void**)&Up, g_Up);
    cudaGetSymbolAddress((void**)&wbc1, g_wbc1);
    cudaGetSymbolAddress((void**)&wbe1, g_wbe1);
    cudaGetSymbolAddress((void**)&wbc2, g_wbc2);
    cudaGetSymbolAddress((void**)&wbe2, g_wbe2);
    cudaGetSymbolAddress((void**)&wac1, g_wac1);
    cudaGetSymbolAddress((void**)&wae1, g_wae1);
    cudaGetSymbolAddress((void**)&wac2, g_wac2);
    cudaGetSymbolAddress((void**)&wae2, g_wae2);

    cudaFuncSetAttribute(gemm_cp<1>, cudaFuncAttributeMaxDynamicSharedMemorySize, GSMEM);
    cudaFuncSetAttribute(gemm_cp<0>, cudaFuncAttributeMaxDynamicSharedMemorySize, GSMEM);
    const int LSMEM = 2 * LSTG + 1024;
    cudaFuncSetAttribute(lora_gemm_part, cudaFuncAttributeMaxDynamicSharedMemorySize, LSMEM);

    // ---- merged pre-splits: 2 launches ----
    {
        SplitArgs a{};
        a.seg[0] = { x,  xh,  T_TOK * D_DIM };
        a.seg[1] = { wi, wih, F_DIM * D_DIM };
        a.seg[2] = { wo, woh, D_DIM * F_DIM };
        dim3 g((T_TOK * D_DIM) / 2048, 3);
        split_multi<<<g, 256>>>(a);
    }
    {
        SplitArgs a{};
        a.seg[0] = { cwi_b, wbc1, F_DIM * 16 };
        a.seg[1] = { ewi_b, wbe1, E_EXP * F_DIM * 16 };
        a.seg[2] = { cwo_b, wbc2, D_DIM * 16 };
        a.seg[3] = { ewo_b, wbe2, E_EXP * D_DIM * 16 };
        a.seg[4] = { cwi_a, wac1, 16 * D_DIM };
        a.seg[5] = { ewi_a, wae1, E_EXP * 16 * D_DIM };
        a.seg[6] = { cwo_a, wac2, 16 * F_DIM };
        a.seg[7] = { ewo_a, wae2, E_EXP * 16 * F_DIM };
        dim3 g((E_EXP * F_DIM * 16) / 2048, 8);
        split_multi<<<g, 256>>>(a);
    }

    // stage 1: split-K=2 lora + combine, then GEMM1
    {
        dim3 gl(T_TOK / 64, 2);
        lora_gemm_part<<<gl, 128, LSMEM>>>(xh, wac1, wae1, eids, Up, D_DIM, D_DIM / 2);
        u_combine<<<(T_TOK * 32) / 1024, 256>>>(Up, U1, 2);
    }
    dim3 g1(F_DIM / 128, T_TOK / 128);
    gemm_cp<1><<<g1, 256, GSMEM>>>(xh, wih, U1, wbc1, wbe1, eids,
                                   nullptr, hid, F_DIM, D_DIM);

    // stage 2: split-K=4 lora + combine, then GEMM2
    {
        dim3 gl(T_TOK / 64, 4);
        lora_gemm_part<<<gl, 128, LSMEM>>>(hid, wac2, wae2, eids, Up, F_DIM, F_DIM / 4);
        u_combine<<<(T_TOK * 32) / 1024, 256>>>(Up, U2, 4);
    }
    dim3 g2(D_DIM / 128, T_TOK / 128);
    gemm_cp<0><<<g2, 256, GSMEM>>>(hid, woh, U2, wbc2, wbe2, eids,
                                   out, nullptr, D_DIM, F_DIM);
}